// round 16
// baseline (speedup 1.0000x reference)
#include <cuda_runtime.h>
#include <cuda_fp16.h>
#include <math.h>
#include <stdint.h>

#define SEQ    2048
#define DM     768
#define NH     4
#define HD     192
#define BATCH  4
#define BHT    16
// 0.05 * log2(e), folded into Q at the k_qkv epilogue
#define SC2    (0.07213475204444817f)

// ---- device scratch ----
__device__ __align__(16) __half g_Xh [BATCH*SEQ*DM];
__device__ __align__(16) __half g_Wh [3*DM*DM];
__device__ __align__(16) __half g_Qh [BHT*SEQ*HD];   // pre-scaled by SC2
__device__ __align__(16) __half g_Kh [BHT*SEQ*HD];
__device__ __align__(16) __half g_Vh [BHT*SEQ*HD];
__device__ __align__(16) __half g_Sch[(size_t)BHT*SEQ*SEQ];   // p = 2^(s*SC2), masked=0
__device__ float  g_pl [BHT*16*SEQ];    // per-(bh,qt,k) partial column sums of p
__device__ __align__(16) __half g_X1p[4*BHT*SEQ*HD]; // split-K partials (4 slots of 512 keys)

// ---------------- helpers ----------------
__device__ __forceinline__ unsigned sptr(const void* p){
    return (unsigned)__cvta_generic_to_shared(p);
}
__device__ __forceinline__ void cpa16(unsigned dst, const void* src){
    asm volatile("cp.async.cg.shared.global [%0], [%1], 16;\n" :: "r"(dst), "l"(src));
}
__device__ __forceinline__ void cpa_commit(){ asm volatile("cp.async.commit_group;\n"); }
__device__ __forceinline__ void cpa_wait_all(){ asm volatile("cp.async.wait_group 0;\n"); }

__device__ __forceinline__ void ldsm4(unsigned r[4], unsigned a){
    asm volatile("ldmatrix.sync.aligned.m8n8.x4.shared.b16 {%0,%1,%2,%3},[%4];\n"
        : "=r"(r[0]),"=r"(r[1]),"=r"(r[2]),"=r"(r[3]) : "r"(a));
}
__device__ __forceinline__ void ldsm4t(unsigned r[4], unsigned a){
    asm volatile("ldmatrix.sync.aligned.m8n8.x4.trans.shared.b16 {%0,%1,%2,%3},[%4];\n"
        : "=r"(r[0]),"=r"(r[1]),"=r"(r[2]),"=r"(r[3]) : "r"(a));
}
__device__ __forceinline__ void mma16816(float* c, const unsigned* a, unsigned b0, unsigned b1){
    asm volatile("mma.sync.aligned.m16n8k16.row.col.f32.f16.f16.f32 "
        "{%0,%1,%2,%3},{%4,%5,%6,%7},{%8,%9},{%0,%1,%2,%3};\n"
        : "+f"(c[0]),"+f"(c[1]),"+f"(c[2]),"+f"(c[3])
        : "r"(a[0]),"r"(a[1]),"r"(a[2]),"r"(a[3]),"r"(b0),"r"(b1));
}
__device__ __forceinline__ unsigned ex2_h2(unsigned s){
    unsigned d;
    asm("ex2.approx.f16x2 %0, %1;" : "=r"(d) : "r"(s));
    return d;
}

// ---------------- fused conversion ----------------
#define NX4 (BATCH*SEQ*DM/4)
#define NW4 (DM*DM/4)
__global__ __launch_bounds__(256) void k_cvt(
    const float* __restrict__ x,
    const float* __restrict__ Wq, const float* __restrict__ Wk, const float* __restrict__ Wv)
{
    int i = blockIdx.x*256 + threadIdx.x;
    const float* src;
    __half* dst;
    int j;
    if (i < NX4){ src = x; dst = g_Xh; j = i; }
    else {
        int t = i - NX4;
        int w = t / NW4;  j = t - w*NW4;
        src = (w==0)?Wq:((w==1)?Wk:Wv);
        dst = g_Wh + (size_t)w*DM*DM;
    }
    float4 v = *(const float4*)(src + (size_t)j*4);
    *(__half2*)&dst[(size_t)j*4]   = __floats2half2_rn(v.x,v.y);
    *(__half2*)&dst[(size_t)j*4+2] = __floats2half2_rn(v.z,v.w);
}

// ============================================================
// K1: QKV projection GEMM-NT, 2-stage cp.async, smem-staged epilogue.
// Q output is pre-scaled by SC2 so k_scores' epilogue needs no FMUL.
// ============================================================
__global__ __launch_bounds__(256,2) void k_qkv(
    const float* __restrict__ bq, const float* __restrict__ bk, const float* __restrict__ bv)
{
    extern __shared__ __align__(16) char smraw[];
    __half* As = (__half*)smraw;            // [2][128][72]
    __half* Bs = As + 2*128*72;             // [2][128][72]

    const int n0 = blockIdx.x*128, m0 = blockIdx.y*128;
    const int tid = threadIdx.x, lane = tid&31, wid = tid>>5;
    const int wm = wid>>2, wn = wid&3;
    const int lrow = lane&15, lcol = (lane>>4)*8;

    float acc[4][4][4] = {};
    const int ldr = tid>>3, ldc = (tid&7)*8;

    #pragma unroll
    for (int i=0;i<4;i++){
        int row = ldr + 32*i;
        cpa16(sptr(&As[(size_t)row*72 + ldc]), &g_Xh[(size_t)(m0+row)*DM + ldc]);
        cpa16(sptr(&Bs[(size_t)row*72 + ldc]), &g_Wh[(size_t)(n0+row)*DM + ldc]);
    }
    cpa_commit();

    const int NIT = DM/64;
    for (int it=0; it<NIT; it++){
        int cur = it & 1;
        cpa_wait_all();
        __syncthreads();
        if (it+1 < NIT){
            int nb = (it+1)&1, kb = (it+1)*64;
            #pragma unroll
            for (int i=0;i<4;i++){
                int row = ldr + 32*i;
                cpa16(sptr(&As[(size_t)(nb*128+row)*72 + ldc]), &g_Xh[(size_t)(m0+row)*DM + kb + ldc]);
                cpa16(sptr(&Bs[(size_t)(nb*128+row)*72 + ldc]), &g_Wh[(size_t)(n0+row)*DM + kb + ldc]);
            }
            cpa_commit();
        }
        const __half* Ab = As + (size_t)cur*128*72;
        const __half* Bb = Bs + (size_t)cur*128*72;
        #pragma unroll
        for (int kk=0;kk<4;kk++){
            unsigned a[4][4], b[2][4];
            #pragma unroll
            for (int mi=0;mi<4;mi++)
                ldsm4(a[mi], sptr(&Ab[(size_t)(wm*64+mi*16+lrow)*72 + kk*16+lcol]));
            #pragma unroll
            for (int np=0;np<2;np++)
                ldsm4(b[np], sptr(&Bb[(size_t)(wn*32+np*16+lrow)*72 + kk*16+lcol]));
            #pragma unroll
            for (int mi=0;mi<4;mi++)
                #pragma unroll
                for (int ni=0;ni<4;ni++)
                    mma16816(acc[mi][ni], a[mi], b[ni>>1][ni&1], b[ni>>1][(ni&1)+2]);
        }
        __syncthreads();
    }

    const int w = n0/DM;
    const int c0 = n0 - w*DM;
    const float* bias = (w==0)?bq:((w==1)?bk:bv);
    __half* Out = (w==0)?g_Qh:((w==1)?g_Kh:g_Vh);
    const float scl = (w==0) ? SC2 : 1.0f;      // fold softmax scale into Q

    __half* Cs = (__half*)smraw;            // [128][136]
    #pragma unroll
    for (int mi=0;mi<4;mi++){
        int r0 = wm*64 + mi*16 + (lane>>2);
        #pragma unroll
        for (int ni=0;ni<4;ni++){
            int cc = wn*32 + ni*8 + (lane&3)*2;
            float b0f = bias[c0+cc], b1f = bias[c0+cc+1];
            #pragma unroll
            for (int p=0;p<2;p++){
                __half2 hv = __floats2half2_rn((acc[mi][ni][2*p]+b0f)*scl,
                                               (acc[mi][ni][2*p+1]+b1f)*scl);
                *(__half2*)&Cs[(size_t)(r0+p*8)*136 + cc] = hv;
            }
        }
    }
    __syncthreads();
    #pragma unroll
    for (int i = tid; i < 128*16; i += 256){
        int row = i>>4, ch = i&15;
        int c = c0 + ch*8;
        int h = c/HD, d = c - h*HD;
        int m = m0 + row;
        int b_ = m>>11, s_ = m&(SEQ-1);
        *(uint4*)&Out[((size_t)((b_*NH+h)*SEQ+s_))*HD + d] = *(uint4*)&Cs[(size_t)row*136 + ch*8];
    }
}

// ============================================================
// K2: p = 2^(Q'K) via ex2.approx.f16x2 (Q pre-scaled), fp16 column
//     sums, smem-staged coalesced score writes. 2-stage cp.async.
// ============================================================
__global__ __launch_bounds__(256,2) void k_scores(const unsigned char* __restrict__ am)
{
    extern __shared__ __align__(16) char smraw[];
    __half* As = (__half*)smraw;            // [2][128][72]
    __half* Bs = As + 2*128*72;
    float*  pl = (float*)(Bs + 2*128*72);

    const int bh = blockIdx.y, b_ = bh>>2;
    int t = blockIdx.x;
    int qt = (int)((sqrtf(8.f*(float)t+1.f)-1.f)*0.5f);
    while ((qt+1)*(qt+2)/2 <= t) ++qt;
    while (qt*(qt+1)/2 > t)      --qt;
    int kt = t - qt*(qt+1)/2;
    const int q0 = qt*128, k0 = kt*128;
    const bool diag = (kt == qt);

    const __half* Qp = g_Qh + (size_t)bh*SEQ*HD;
    const __half* Kp = g_Kh + (size_t)bh*SEQ*HD;
    __half* Sp = g_Sch + (size_t)bh*SEQ*SEQ;

    const int tid = threadIdx.x, lane = tid&31, wid = tid>>5;
    const int wm = wid>>2, wn = wid&3;
    const int lrow = lane&15, lcol = (lane>>4)*8;
    const int ldr = tid>>3, ldc = (tid&7)*8;

    float acc[4][4][4] = {};

    #pragma unroll
    for (int i=0;i<4;i++){
        int row = ldr + 32*i;
        cpa16(sptr(&As[(size_t)row*72 + ldc]), &Qp[(size_t)(q0+row)*HD + ldc]);
        cpa16(sptr(&Bs[(size_t)row*72 + ldc]), &Kp[(size_t)(k0+row)*HD + ldc]);
    }
    cpa_commit();

    const int NIT = HD/64;
    for (int it=0; it<NIT; it++){
        int cur = it & 1;
        cpa_wait_all();
        __syncthreads();
        if (it+1 < NIT){
            int nb = (it+1)&1, kb = (it+1)*64;
            #pragma unroll
            for (int i=0;i<4;i++){
                int row = ldr + 32*i;
                cpa16(sptr(&As[(size_t)(nb*128+row)*72 + ldc]), &Qp[(size_t)(q0+row)*HD + kb + ldc]);
                cpa16(sptr(&Bs[(size_t)(nb*128+row)*72 + ldc]), &Kp[(size_t)(k0+row)*HD + kb + ldc]);
            }
            cpa_commit();
        }
        const __half* Ab = As + (size_t)cur*128*72;
        const __half* Bb = Bs + (size_t)cur*128*72;
        #pragma unroll
        for (int kk=0;kk<4;kk++){
            unsigned a[4][4], b[2][4];
            #pragma unroll
            for (int mi=0;mi<4;mi++)
                ldsm4(a[mi], sptr(&Ab[(size_t)(wm*64+mi*16+lrow)*72 + kk*16+lcol]));
            #pragma unroll
            for (int np=0;np<2;np++)
                ldsm4(b[np], sptr(&Bb[(size_t)(wn*32+np*16+lrow)*72 + kk*16+lcol]));
            #pragma unroll
            for (int mi=0;mi<4;mi++)
                #pragma unroll
                for (int ni=0;ni<4;ni++)
                    mma16816(acc[mi][ni], a[mi], b[ni>>1][ni&1], b[ni>>1][(ni&1)+2]);
        }
        __syncthreads();
    }

    // ---- epilogue: fp16 ex2, fp16 column sums, stage p into smem ----
    __half* Ps = (__half*)smraw;            // [128][136], reuses As region
    __half2 colsum[4];
    #pragma unroll
    for (int ni=0;ni<4;ni++) colsum[ni] = __floats2half2_rn(0.f,0.f);

    #pragma unroll
    for (int mi=0;mi<4;mi++){
        int r0 = wm*64 + mi*16 + (lane>>2);
        #pragma unroll
        for (int p=0;p<2;p++){
            int qr = r0 + p*8;
            int q = q0 + qr;
            bool pad = am[b_*SEQ + q] != 0;
            #pragma unroll
            for (int ni=0;ni<4;ni++){
                int kk2 = wn*32 + ni*8 + (lane&3)*2;
                int k = k0 + kk2;
                float v0, v1;
                if (diag){
                    v0 = (k   > q || pad) ? -60000.f : acc[mi][ni][2*p];
                    v1 = (k+1 > q || pad) ? -60000.f : acc[mi][ni][2*p+1];
                } else {
                    v0 = pad ? -60000.f : acc[mi][ni][2*p];
                    v1 = pad ? -60000.f : acc[mi][ni][2*p+1];
                }
                __half2 hs = __floats2half2_rn(v0,v1);
                unsigned pe_u = ex2_h2(*(unsigned*)&hs);     // 2^(-60000) -> 0
                __half2 pe = *(__half2*)&pe_u;
                *(__half2*)&Ps[(size_t)qr*136 + kk2] = pe;
                colsum[ni] = __hadd2(colsum[ni], pe);
            }
        }
    }
    float coll[4][2];
    #pragma unroll
    for (int ni=0;ni<4;ni++){
        float2 f = __half22float2(colsum[ni]);
        coll[ni][0] = f.x; coll[ni][1] = f.y;
    }
    #pragma unroll
    for (int off=4; off<32; off<<=1){
        #pragma unroll
        for (int ni=0;ni<4;ni++){
            coll[ni][0] += __shfl_xor_sync(0xffffffffu, coll[ni][0], off);
            coll[ni][1] += __shfl_xor_sync(0xffffffffu, coll[ni][1], off);
        }
    }
    if (lane < 4){
        #pragma unroll
        for (int ni=0;ni<4;ni++){
            int col = wn*32 + ni*8 + lane*2;
            pl[wm*128 + col]     = coll[ni][0];
            pl[wm*128 + col + 1] = coll[ni][1];
        }
    }
    __syncthreads();
    #pragma unroll
    for (int i = tid; i < 128*16; i += 256){
        int row = i>>4, ch = i&15;
        *(uint4*)&Sp[(size_t)(q0+row)*SEQ + k0 + ch*8] = *(uint4*)&Ps[(size_t)row*136 + ch*8];
    }
    if (tid < 128){
        size_t o = ((size_t)(bh*16 + qt))*SEQ + k0 + tid;
        g_pl[o] = pl[tid] + pl[128+tid];
    }
}

// ============================================================
// K3: fused inv + V-fold. grid (SEQ/16=128, BHT), 16 rows, 128 thr
// (2x block count vs R13 — latency-bound kernel, more CTAs in flight)
// ============================================================
__global__ __launch_bounds__(128) void k_foldv()
{
    const int bx = blockIdx.x, bh = blockIdx.y;
    const int r0 = bx*16;
    const int kt = r0 >> 7;
    const int tid = threadIdx.x;
    __shared__ float inv_s[16];

    if (tid < 16){
        int k = r0 + tid;
        float l = 0.f;
        #pragma unroll 4
        for (int qt = kt; qt < 16; qt++)
            l += g_pl[((size_t)(bh*16 + qt))*SEQ + k];
        inv_s[tid] = 1.0f/l;
    }
    __syncthreads();

    __half* Vp = g_Vh + ((size_t)bh*SEQ + r0)*HD;
    // 16 rows x 24 uint4 = 384 items, 3 per thread
    #pragma unroll
    for (int i = tid; i < 16*24; i += 128){
        int row = i/24, c4 = i - row*24;
        float inv = inv_s[row];
        uint4 v = *(uint4*)&Vp[(size_t)row*HD + c4*8];
        __half2* h = (__half2*)&v;
        #pragma unroll
        for (int j=0;j<4;j++){
            float2 f = __half22float2(h[j]);
            h[j] = __floats2half2_rn(f.x*inv, f.y*inv);
        }
        *(uint4*)&Vp[(size_t)row*HD + c4*8] = v;
    }
}

// ============================================================
// K4: X1 partial = p @ V' — pure GEMM, split-K of 512 keys (R13 form)
// ============================================================
__global__ __launch_bounds__(256,2) void k_av()
{
    extern __shared__ __align__(16) char smraw[];
    __half* Ss = (__half*)smraw;            // [2][128][72]  p tiles
    __half* Vs = Ss + 2*128*72;             // [2][64][200]  V' tiles

    int idx = 39 - (int)blockIdx.x;
    int g, base;
    if      (idx < 4)  { g=0; base=0;  }
    else if (idx < 12) { g=1; base=4;  }
    else if (idx < 24) { g=2; base=12; }
    else               { g=3; base=24; }
    int off = idx - base;
    const int qt = 4*g + off/(g+1);
    const int ks = off % (g+1);

    const int bh = blockIdx.y;
    const int q0 = qt*128;
    const int kstart = ks*512;
    const int kend   = min(kstart+512, (qt+1)*128);

    const __half* Vp = g_Vh + (size_t)bh*SEQ*HD;
    const __half* Sp = g_Sch + (size_t)bh*SEQ*SEQ;

    const int tid = threadIdx.x, lane = tid&31, wid = tid>>5;
    const int wm = wid>>2, wn = wid&3;
    const int lrow = lane&15, lcol = (lane>>4)*8;

    float acc[4][6][4] = {};
    const int srow = tid>>3, svc = (tid&7)*8;

    {
        #pragma unroll
        for (int i=0;i<4;i++){
            int row = srow + 32*i;
            cpa16(sptr(&Ss[(size_t)row*72 + svc]), &Sp[(size_t)(q0+row)*SEQ + kstart + svc]);
        }
        #pragma unroll
        for (int i=0;i<6;i++){
            int ii = tid + 256*i;
            int row = ii/24, vc = (ii%24)*8;
            cpa16(sptr(&Vs[(size_t)row*200 + vc]), &Vp[(size_t)(kstart+row)*HD + vc]);
        }
        cpa_commit();
    }

    const int NIT = (kend - kstart) >> 6;
    for (int it=0; it<NIT; it++){
        int cur = it & 1;
        cpa_wait_all();
        __syncthreads();
        if (it+1 < NIT){
            int nb = (it+1)&1, kb = kstart + (it+1)*64;
            #pragma unroll
            for (int i=0;i<4;i++){
                int row = srow + 32*i;
                cpa16(sptr(&Ss[(size_t)(nb*128+row)*72 + svc]), &Sp[(size_t)(q0+row)*SEQ + kb + svc]);
            }
            #pragma unroll
            for (int i=0;i<6;i++){
                int ii = tid + 256*i;
                int row = ii/24, vc = (ii%24)*8;
                cpa16(sptr(&Vs[(size_t)(nb*64+row)*200 + vc]), &Vp[(size_t)(kb+row)*HD + vc]);
            }
            cpa_commit();
        }
        const __half* Sb = Ss + (size_t)cur*128*72;
        const __half* Vb = Vs + (size_t)cur*64*200;
        #pragma unroll
        for (int kk=0;kk<4;kk++){
            unsigned a[4][4], b[3][4];
            #pragma unroll
            for (int mi=0;mi<4;mi++)
                ldsm4(a[mi], sptr(&Sb[(size_t)(wm*64+mi*16+lrow)*72 + kk*16+lcol]));
            #pragma unroll
            for (int np=0;np<3;np++)
                ldsm4t(b[np], sptr(&Vb[(size_t)(kk*16+lrow)*200 + wn*48+np*16+lcol]));
            #pragma unroll
            for (int mi=0;mi<4;mi++)
                #pragma unroll
                for (int ni=0;ni<6;ni++)
                    mma16816(acc[mi][ni], a[mi], b[ni>>1][(ni&1)*2], b[ni>>1][(ni&1)*2+1]);
        }
    }

    // stage X1 tile into smem, then coalesced copy-out
    __syncthreads();
    __half* Xs = (__half*)smraw;            // [128][200]
    #pragma unroll
    for (int mi=0;mi<4;mi++){
        int r0 = wm*64 + mi*16 + (lane>>2);
        #pragma unroll
        for (int ni=0;ni<6;ni++){
            int d = wn*48 + ni*8 + (lane&3)*2;
            #pragma unroll
            for (int p=0;p<2;p++){
                *(__half2*)&Xs[(size_t)(r0+p*8)*200 + d] =
                    __floats2half2_rn(acc[mi][ni][2*p], acc[mi][ni][2*p+1]);
            }
        }
    }
    __syncthreads();
    __half* Xp = g_X1p + (size_t)ks*BHT*SEQ*HD;
    #pragma unroll
    for (int i = tid; i < 128*24; i += 256){
        int row = i/24, ch = i - (i/24)*24;
        *(uint4*)&Xp[((size_t)(bh*SEQ + q0 + row))*HD + ch*8] = *(uint4*)&Xs[(size_t)row*200 + ch*8];
    }
}

// ============================================================
// K5: y = x + sum(X1 partials), LayerNorm — 384 thr, 2 ch/thread
// ============================================================
__global__ __launch_bounds__(384) void k_ln(
    const float* __restrict__ x,
    const float* __restrict__ gamma,
    const float* __restrict__ beta,
    float* __restrict__ out)
{
    int row = blockIdx.x;
    int b_ = row >> 11, s_ = row & (SEQ-1);
    int tid = threadIdx.x;
    int ns = (s_ >> 9) + 1;
    int c = tid*2;

    __shared__ float rs[12], rq[12];
    __shared__ float s_mu, s_inv;

    int h_ = c/HD, d_ = c - h_*HD;
    size_t o = ((size_t)((b_*NH+h_)*SEQ+s_))*HD + d_;
    float2 xv = *(const float2*)&x[(size_t)row*DM + c];
    float v0 = xv.x, v1 = xv.y;
    for (int s = 0; s < ns; s++){
        __half2 hp = *(const __half2*)&g_X1p[(size_t)s*BHT*SEQ*HD + o];
        float2 f = __half22float2(hp);
        v0 += f.x; v1 += f.y;
    }
    float sum = v0 + v1;
    float sq  = v0*v0 + v1*v1;

    #pragma unroll
    for (int of = 16; of; of >>= 1){
        sum += __shfl_down_sync(0xffffffffu, sum, of);
        sq  += __shfl_down_sync(0xffffffffu, sq , of);
    }
    int wid = tid >> 5, lane = tid & 31;
    if (lane == 0){ rs[wid] = sum; rq[wid] = sq; }
    __syncthreads();
    if (tid < 32){
        sum = (tid < 12) ? rs[tid] : 0.0f;
        sq  = (tid < 12) ? rq[tid] : 0.0f;
        #pragma unroll
        for (int of = 16; of; of >>= 1){
            sum += __shfl_down_sync(0xffffffffu, sum, of);
            sq  += __shfl_down_sync(0xffffffffu, sq , of);
        }
        if (tid == 0){
            float mu  = sum * (1.0f/DM);
            float var = sq  * (1.0f/DM) - mu*mu;
            s_mu = mu;
            s_inv = rsqrtf(var + 1e-5f);
        }
    }
    __syncthreads();
    float mu = s_mu, inv = s_inv;
    float2 gv = *(const float2*)&gamma[c];
    float2 bv = *(const float2*)&beta[c];
    float2 ov;
    ov.x = (v0 - mu)*inv*gv.x + bv.x;
    ov.y = (v1 - mu)*inv*gv.y + bv.y;
    *(float2*)&out[(size_t)row*DM + c] = ov;
}

// ============================================================
extern "C" void kernel_launch(void* const* d_in, const int* in_sizes, int n_in,
                              void* d_out, int out_size)
{
    const float*         x     = (const float*)d_in[0];
    const unsigned char* am    = (const unsigned char*)d_in[1];
    const float*         Wq    = (const float*)d_in[2];
    const float*         bq    = (const float*)d_in[3];
    const float*         Wk    = (const float*)d_in[4];
    const float*         bk    = (const float*)d_in[5];
    const float*         Wv    = (const float*)d_in[6];
    const float*         bv    = (const float*)d_in[7];
    const float*         gamma = (const float*)d_in[8];
    const float*         beta  = (const float*)d_in[9];
    float*               out   = (float*)d_out;
    (void)in_sizes; (void)n_in; (void)out_size;

    const int SM_QKV = 2*128*72*2*2;                    // 73728
    const int SM_SC  = 2*128*72*2*2 + 2*128*4;          // 74752
    const int SM_AV  = (2*128*72 + 2*64*200)*2;         // 88064

    cudaFuncSetAttribute(k_qkv,    cudaFuncAttributeMaxDynamicSharedMemorySize, SM_QKV);
    cudaFuncSetAttribute(k_scores, cudaFuncAttributeMaxDynamicSharedMemorySize, SM_SC);
    cudaFuncSetAttribute(k_av,     cudaFuncAttributeMaxDynamicSharedMemorySize, SM_AV);

    k_cvt<<<(NX4 + 3*NW4)/256, 256>>>(x, Wq, Wk, Wv);

    k_qkv<<<dim3(3*DM/128, BATCH*SEQ/128), 256, SM_QKV>>>(bq, bk, bv);

    const int NT = (SEQ/128)*(SEQ/128 + 1)/2;   // 136 lower-tri tiles
    k_scores<<<dim3(NT, BHT), 256, SM_SC>>>(am);

    k_foldv<<<dim3(SEQ/16, BHT), 128>>>();

    k_av<<<dim3(40, BHT), 256, SM_AV>>>();

    k_ln<<<BATCH*SEQ, 384>>>(x, gamma, beta, out);
}

// round 17
// speedup vs baseline: 1.0578x; 1.0578x over previous
#include <cuda_runtime.h>
#include <cuda_fp16.h>
#include <math.h>
#include <stdint.h>

#define SEQ    2048
#define DM     768
#define NH     4
#define HD     192
#define BATCH  4
#define BHT    16
// 0.05 * log2(e), folded into Q at the k_qkv epilogue
#define SC2    (0.07213475204444817f)

// ---- device scratch ----
__device__ __align__(16) __half g_Xh [BATCH*SEQ*DM];
__device__ __align__(16) __half g_Wh [3*DM*DM];
__device__ __align__(16) __half g_Qh [BHT*SEQ*HD];   // pre-scaled by SC2
__device__ __align__(16) __half g_Kh [BHT*SEQ*HD];
__device__ __align__(16) __half g_Vh [BHT*SEQ*HD];
__device__ __align__(16) __half g_Sch[(size_t)BHT*SEQ*SEQ];   // p = 2^(s*SC2), masked=0
__device__ float  g_pl [BHT*16*SEQ];    // per-(bh,qt,k) partial column sums of p
__device__ __align__(16) __half g_X1p[4*BHT*SEQ*HD]; // split-K partials (4 slots of 512 keys)

// ---------------- helpers ----------------
__device__ __forceinline__ unsigned sptr(const void* p){
    return (unsigned)__cvta_generic_to_shared(p);
}
__device__ __forceinline__ void cpa16(unsigned dst, const void* src){
    asm volatile("cp.async.cg.shared.global [%0], [%1], 16;\n" :: "r"(dst), "l"(src));
}
__device__ __forceinline__ void cpa_commit(){ asm volatile("cp.async.commit_group;\n"); }
__device__ __forceinline__ void cpa_wait_all(){ asm volatile("cp.async.wait_group 0;\n"); }

__device__ __forceinline__ void ldsm4(unsigned r[4], unsigned a){
    asm volatile("ldmatrix.sync.aligned.m8n8.x4.shared.b16 {%0,%1,%2,%3},[%4];\n"
        : "=r"(r[0]),"=r"(r[1]),"=r"(r[2]),"=r"(r[3]) : "r"(a));
}
__device__ __forceinline__ void ldsm4t(unsigned r[4], unsigned a){
    asm volatile("ldmatrix.sync.aligned.m8n8.x4.trans.shared.b16 {%0,%1,%2,%3},[%4];\n"
        : "=r"(r[0]),"=r"(r[1]),"=r"(r[2]),"=r"(r[3]) : "r"(a));
}
__device__ __forceinline__ void mma16816(float* c, const unsigned* a, unsigned b0, unsigned b1){
    asm volatile("mma.sync.aligned.m16n8k16.row.col.f32.f16.f16.f32 "
        "{%0,%1,%2,%3},{%4,%5,%6,%7},{%8,%9},{%0,%1,%2,%3};\n"
        : "+f"(c[0]),"+f"(c[1]),"+f"(c[2]),"+f"(c[3])
        : "r"(a[0]),"r"(a[1]),"r"(a[2]),"r"(a[3]),"r"(b0),"r"(b1));
}
__device__ __forceinline__ unsigned ex2_h2(unsigned s){
    unsigned d;
    asm("ex2.approx.f16x2 %0, %1;" : "=r"(d) : "r"(s));
    return d;
}

// ---------------- fused conversion ----------------
#define NX4 (BATCH*SEQ*DM/4)
#define NW4 (DM*DM/4)
__global__ __launch_bounds__(256) void k_cvt(
    const float* __restrict__ x,
    const float* __restrict__ Wq, const float* __restrict__ Wk, const float* __restrict__ Wv)
{
    int i = blockIdx.x*256 + threadIdx.x;
    const float* src;
    __half* dst;
    int j;
    if (i < NX4){ src = x; dst = g_Xh; j = i; }
    else {
        int t = i - NX4;
        int w = t / NW4;  j = t - w*NW4;
        src = (w==0)?Wq:((w==1)?Wk:Wv);
        dst = g_Wh + (size_t)w*DM*DM;
    }
    float4 v = *(const float4*)(src + (size_t)j*4);
    *(__half2*)&dst[(size_t)j*4]   = __floats2half2_rn(v.x,v.y);
    *(__half2*)&dst[(size_t)j*4+2] = __floats2half2_rn(v.z,v.w);
}

// ============================================================
// K1: QKV projection GEMM-NT, 2-stage cp.async, smem-staged epilogue.
// Q output is pre-scaled by SC2 so k_scores' epilogue needs no FMUL.
// ============================================================
__global__ __launch_bounds__(256,2) void k_qkv(
    const float* __restrict__ bq, const float* __restrict__ bk, const float* __restrict__ bv)
{
    extern __shared__ __align__(16) char smraw[];
    __half* As = (__half*)smraw;            // [2][128][72]
    __half* Bs = As + 2*128*72;             // [2][128][72]

    const int n0 = blockIdx.x*128, m0 = blockIdx.y*128;
    const int tid = threadIdx.x, lane = tid&31, wid = tid>>5;
    const int wm = wid>>2, wn = wid&3;
    const int lrow = lane&15, lcol = (lane>>4)*8;

    float acc[4][4][4] = {};
    const int ldr = tid>>3, ldc = (tid&7)*8;

    #pragma unroll
    for (int i=0;i<4;i++){
        int row = ldr + 32*i;
        cpa16(sptr(&As[(size_t)row*72 + ldc]), &g_Xh[(size_t)(m0+row)*DM + ldc]);
        cpa16(sptr(&Bs[(size_t)row*72 + ldc]), &g_Wh[(size_t)(n0+row)*DM + ldc]);
    }
    cpa_commit();

    const int NIT = DM/64;
    for (int it=0; it<NIT; it++){
        int cur = it & 1;
        cpa_wait_all();
        __syncthreads();
        if (it+1 < NIT){
            int nb = (it+1)&1, kb = (it+1)*64;
            #pragma unroll
            for (int i=0;i<4;i++){
                int row = ldr + 32*i;
                cpa16(sptr(&As[(size_t)(nb*128+row)*72 + ldc]), &g_Xh[(size_t)(m0+row)*DM + kb + ldc]);
                cpa16(sptr(&Bs[(size_t)(nb*128+row)*72 + ldc]), &g_Wh[(size_t)(n0+row)*DM + kb + ldc]);
            }
            cpa_commit();
        }
        const __half* Ab = As + (size_t)cur*128*72;
        const __half* Bb = Bs + (size_t)cur*128*72;
        #pragma unroll
        for (int kk=0;kk<4;kk++){
            unsigned a[4][4], b[2][4];
            #pragma unroll
            for (int mi=0;mi<4;mi++)
                ldsm4(a[mi], sptr(&Ab[(size_t)(wm*64+mi*16+lrow)*72 + kk*16+lcol]));
            #pragma unroll
            for (int np=0;np<2;np++)
                ldsm4(b[np], sptr(&Bb[(size_t)(wn*32+np*16+lrow)*72 + kk*16+lcol]));
            #pragma unroll
            for (int mi=0;mi<4;mi++)
                #pragma unroll
                for (int ni=0;ni<4;ni++)
                    mma16816(acc[mi][ni], a[mi], b[ni>>1][ni&1], b[ni>>1][(ni&1)+2]);
        }
        __syncthreads();
    }

    const int w = n0/DM;
    const int c0 = n0 - w*DM;
    const float* bias = (w==0)?bq:((w==1)?bk:bv);
    __half* Out = (w==0)?g_Qh:((w==1)?g_Kh:g_Vh);
    const float scl = (w==0) ? SC2 : 1.0f;      // fold softmax scale into Q

    __half* Cs = (__half*)smraw;            // [128][136]
    #pragma unroll
    for (int mi=0;mi<4;mi++){
        int r0 = wm*64 + mi*16 + (lane>>2);
        #pragma unroll
        for (int ni=0;ni<4;ni++){
            int cc = wn*32 + ni*8 + (lane&3)*2;
            float b0f = bias[c0+cc], b1f = bias[c0+cc+1];
            #pragma unroll
            for (int p=0;p<2;p++){
                __half2 hv = __floats2half2_rn((acc[mi][ni][2*p]+b0f)*scl,
                                               (acc[mi][ni][2*p+1]+b1f)*scl);
                *(__half2*)&Cs[(size_t)(r0+p*8)*136 + cc] = hv;
            }
        }
    }
    __syncthreads();
    #pragma unroll
    for (int i = tid; i < 128*16; i += 256){
        int row = i>>4, ch = i&15;
        int c = c0 + ch*8;
        int h = c/HD, d = c - h*HD;
        int m = m0 + row;
        int b_ = m>>11, s_ = m&(SEQ-1);
        *(uint4*)&Out[((size_t)((b_*NH+h)*SEQ+s_))*HD + d] = *(uint4*)&Cs[(size_t)row*136 + ch*8];
    }
}

// ============================================================
// K2: p = 2^(Q'K) via ex2.approx.f16x2 (Q pre-scaled), fp16 column
//     sums, smem-staged coalesced score writes. 2-stage cp.async.
// ============================================================
__global__ __launch_bounds__(256,2) void k_scores(const unsigned char* __restrict__ am)
{
    extern __shared__ __align__(16) char smraw[];
    __half* As = (__half*)smraw;            // [2][128][72]
    __half* Bs = As + 2*128*72;
    float*  pl = (float*)(Bs + 2*128*72);

    const int bh = blockIdx.y, b_ = bh>>2;
    int t = blockIdx.x;
    int qt = (int)((sqrtf(8.f*(float)t+1.f)-1.f)*0.5f);
    while ((qt+1)*(qt+2)/2 <= t) ++qt;
    while (qt*(qt+1)/2 > t)      --qt;
    int kt = t - qt*(qt+1)/2;
    const int q0 = qt*128, k0 = kt*128;
    const bool diag = (kt == qt);

    const __half* Qp = g_Qh + (size_t)bh*SEQ*HD;
    const __half* Kp = g_Kh + (size_t)bh*SEQ*HD;
    __half* Sp = g_Sch + (size_t)bh*SEQ*SEQ;

    const int tid = threadIdx.x, lane = tid&31, wid = tid>>5;
    const int wm = wid>>2, wn = wid&3;
    const int lrow = lane&15, lcol = (lane>>4)*8;
    const int ldr = tid>>3, ldc = (tid&7)*8;

    float acc[4][4][4] = {};

    #pragma unroll
    for (int i=0;i<4;i++){
        int row = ldr + 32*i;
        cpa16(sptr(&As[(size_t)row*72 + ldc]), &Qp[(size_t)(q0+row)*HD + ldc]);
        cpa16(sptr(&Bs[(size_t)row*72 + ldc]), &Kp[(size_t)(k0+row)*HD + ldc]);
    }
    cpa_commit();

    const int NIT = HD/64;
    for (int it=0; it<NIT; it++){
        int cur = it & 1;
        cpa_wait_all();
        __syncthreads();
        if (it+1 < NIT){
            int nb = (it+1)&1, kb = (it+1)*64;
            #pragma unroll
            for (int i=0;i<4;i++){
                int row = ldr + 32*i;
                cpa16(sptr(&As[(size_t)(nb*128+row)*72 + ldc]), &Qp[(size_t)(q0+row)*HD + kb + ldc]);
                cpa16(sptr(&Bs[(size_t)(nb*128+row)*72 + ldc]), &Kp[(size_t)(k0+row)*HD + kb + ldc]);
            }
            cpa_commit();
        }
        const __half* Ab = As + (size_t)cur*128*72;
        const __half* Bb = Bs + (size_t)cur*128*72;
        #pragma unroll
        for (int kk=0;kk<4;kk++){
            unsigned a[4][4], b[2][4];
            #pragma unroll
            for (int mi=0;mi<4;mi++)
                ldsm4(a[mi], sptr(&Ab[(size_t)(wm*64+mi*16+lrow)*72 + kk*16+lcol]));
            #pragma unroll
            for (int np=0;np<2;np++)
                ldsm4(b[np], sptr(&Bb[(size_t)(wn*32+np*16+lrow)*72 + kk*16+lcol]));
            #pragma unroll
            for (int mi=0;mi<4;mi++)
                #pragma unroll
                for (int ni=0;ni<4;ni++)
                    mma16816(acc[mi][ni], a[mi], b[ni>>1][ni&1], b[ni>>1][(ni&1)+2]);
        }
        __syncthreads();
    }

    // ---- epilogue: fp16 ex2, fp16 column sums, stage p into smem ----
    __half* Ps = (__half*)smraw;            // [128][136], reuses As region
    __half2 colsum[4];
    #pragma unroll
    for (int ni=0;ni<4;ni++) colsum[ni] = __floats2half2_rn(0.f,0.f);

    #pragma unroll
    for (int mi=0;mi<4;mi++){
        int r0 = wm*64 + mi*16 + (lane>>2);
        #pragma unroll
        for (int p=0;p<2;p++){
            int qr = r0 + p*8;
            int q = q0 + qr;
            bool pad = am[b_*SEQ + q] != 0;
            #pragma unroll
            for (int ni=0;ni<4;ni++){
                int kk2 = wn*32 + ni*8 + (lane&3)*2;
                int k = k0 + kk2;
                float v0, v1;
                if (diag){
                    v0 = (k   > q || pad) ? -60000.f : acc[mi][ni][2*p];
                    v1 = (k+1 > q || pad) ? -60000.f : acc[mi][ni][2*p+1];
                } else {
                    v0 = pad ? -60000.f : acc[mi][ni][2*p];
                    v1 = pad ? -60000.f : acc[mi][ni][2*p+1];
                }
                __half2 hs = __floats2half2_rn(v0,v1);
                unsigned pe_u = ex2_h2(*(unsigned*)&hs);     // 2^(-60000) -> 0
                __half2 pe = *(__half2*)&pe_u;
                *(__half2*)&Ps[(size_t)qr*136 + kk2] = pe;
                colsum[ni] = __hadd2(colsum[ni], pe);
            }
        }
    }
    float coll[4][2];
    #pragma unroll
    for (int ni=0;ni<4;ni++){
        float2 f = __half22float2(colsum[ni]);
        coll[ni][0] = f.x; coll[ni][1] = f.y;
    }
    #pragma unroll
    for (int off=4; off<32; off<<=1){
        #pragma unroll
        for (int ni=0;ni<4;ni++){
            coll[ni][0] += __shfl_xor_sync(0xffffffffu, coll[ni][0], off);
            coll[ni][1] += __shfl_xor_sync(0xffffffffu, coll[ni][1], off);
        }
    }
    if (lane < 4){
        #pragma unroll
        for (int ni=0;ni<4;ni++){
            int col = wn*32 + ni*8 + lane*2;
            pl[wm*128 + col]     = coll[ni][0];
            pl[wm*128 + col + 1] = coll[ni][1];
        }
    }
    __syncthreads();
    #pragma unroll
    for (int i = tid; i < 128*16; i += 256){
        int row = i>>4, ch = i&15;
        *(uint4*)&Sp[(size_t)(q0+row)*SEQ + k0 + ch*8] = *(uint4*)&Ps[(size_t)row*136 + ch*8];
    }
    if (tid < 128){
        size_t o = ((size_t)(bh*16 + qt))*SEQ + k0 + tid;
        g_pl[o] = pl[tid] + pl[128+tid];
    }
}

// ============================================================
// K3: fused inv + V-fold. grid (SEQ/32=64, BHT), 32 rows/block. (R13)
// ============================================================
__global__ __launch_bounds__(256) void k_foldv()
{
    const int bx = blockIdx.x, bh = blockIdx.y;
    const int r0 = bx*32;
    const int kt = r0 >> 7;
    const int tid = threadIdx.x;
    __shared__ float inv_s[32];

    if (tid < 32){
        int k = r0 + tid;
        float l = 0.f;
        #pragma unroll 4
        for (int qt = kt; qt < 16; qt++)
            l += g_pl[((size_t)(bh*16 + qt))*SEQ + k];
        inv_s[tid] = 1.0f/l;
    }
    __syncthreads();

    __half* Vp = g_Vh + ((size_t)bh*SEQ + r0)*HD;
    #pragma unroll
    for (int i = tid; i < 32*24; i += 256){
        int row = i/24, c4 = i - row*24;
        float inv = inv_s[row];
        uint4 v = *(uint4*)&Vp[(size_t)row*HD + c4*8];
        __half2* h = (__half2*)&v;
        #pragma unroll
        for (int j=0;j<4;j++){
            float2 f = __half22float2(h[j]);
            h[j] = __floats2half2_rn(f.x*inv, f.y*inv);
        }
        *(uint4*)&Vp[(size_t)row*HD + c4*8] = v;
    }
}

// ============================================================
// K4: X1 partial = p @ V' — pure GEMM, split-K of 512 keys (R13)
// ============================================================
__global__ __launch_bounds__(256,2) void k_av()
{
    extern __shared__ __align__(16) char smraw[];
    __half* Ss = (__half*)smraw;            // [2][128][72]  p tiles
    __half* Vs = Ss + 2*128*72;             // [2][64][200]  V' tiles

    int idx = 39 - (int)blockIdx.x;
    int g, base;
    if      (idx < 4)  { g=0; base=0;  }
    else if (idx < 12) { g=1; base=4;  }
    else if (idx < 24) { g=2; base=12; }
    else               { g=3; base=24; }
    int off = idx - base;
    const int qt = 4*g + off/(g+1);
    const int ks = off % (g+1);

    const int bh = blockIdx.y;
    const int q0 = qt*128;
    const int kstart = ks*512;
    const int kend   = min(kstart+512, (qt+1)*128);

    const __half* Vp = g_Vh + (size_t)bh*SEQ*HD;
    const __half* Sp = g_Sch + (size_t)bh*SEQ*SEQ;

    const int tid = threadIdx.x, lane = tid&31, wid = tid>>5;
    const int wm = wid>>2, wn = wid&3;
    const int lrow = lane&15, lcol = (lane>>4)*8;

    float acc[4][6][4] = {};
    const int srow = tid>>3, svc = (tid&7)*8;

    {
        #pragma unroll
        for (int i=0;i<4;i++){
            int row = srow + 32*i;
            cpa16(sptr(&Ss[(size_t)row*72 + svc]), &Sp[(size_t)(q0+row)*SEQ + kstart + svc]);
        }
        #pragma unroll
        for (int i=0;i<6;i++){
            int ii = tid + 256*i;
            int row = ii/24, vc = (ii%24)*8;
            cpa16(sptr(&Vs[(size_t)row*200 + vc]), &Vp[(size_t)(kstart+row)*HD + vc]);
        }
        cpa_commit();
    }

    const int NIT = (kend - kstart) >> 6;
    for (int it=0; it<NIT; it++){
        int cur = it & 1;
        cpa_wait_all();
        __syncthreads();
        if (it+1 < NIT){
            int nb = (it+1)&1, kb = kstart + (it+1)*64;
            #pragma unroll
            for (int i=0;i<4;i++){
                int row = srow + 32*i;
                cpa16(sptr(&Ss[(size_t)(nb*128+row)*72 + svc]), &Sp[(size_t)(q0+row)*SEQ + kb + svc]);
            }
            #pragma unroll
            for (int i=0;i<6;i++){
                int ii = tid + 256*i;
                int row = ii/24, vc = (ii%24)*8;
                cpa16(sptr(&Vs[(size_t)(nb*64+row)*200 + vc]), &Vp[(size_t)(kb+row)*HD + vc]);
            }
            cpa_commit();
        }
        const __half* Sb = Ss + (size_t)cur*128*72;
        const __half* Vb = Vs + (size_t)cur*64*200;
        #pragma unroll
        for (int kk=0;kk<4;kk++){
            unsigned a[4][4], b[3][4];
            #pragma unroll
            for (int mi=0;mi<4;mi++)
                ldsm4(a[mi], sptr(&Sb[(size_t)(wm*64+mi*16+lrow)*72 + kk*16+lcol]));
            #pragma unroll
            for (int np=0;np<3;np++)
                ldsm4t(b[np], sptr(&Vb[(size_t)(kk*16+lrow)*200 + wn*48+np*16+lcol]));
            #pragma unroll
            for (int mi=0;mi<4;mi++)
                #pragma unroll
                for (int ni=0;ni<6;ni++)
                    mma16816(acc[mi][ni], a[mi], b[ni>>1][(ni&1)*2], b[ni>>1][(ni&1)*2+1]);
        }
    }

    // stage X1 tile into smem, then coalesced copy-out
    __syncthreads();
    __half* Xs = (__half*)smraw;            // [128][200]
    #pragma unroll
    for (int mi=0;mi<4;mi++){
        int r0 = wm*64 + mi*16 + (lane>>2);
        #pragma unroll
        for (int ni=0;ni<6;ni++){
            int d = wn*48 + ni*8 + (lane&3)*2;
            #pragma unroll
            for (int p=0;p<2;p++){
                *(__half2*)&Xs[(size_t)(r0+p*8)*200 + d] =
                    __floats2half2_rn(acc[mi][ni][2*p], acc[mi][ni][2*p+1]);
            }
        }
    }
    __syncthreads();
    __half* Xp = g_X1p + (size_t)ks*BHT*SEQ*HD;
    #pragma unroll
    for (int i = tid; i < 128*24; i += 256){
        int row = i/24, ch = i - (i/24)*24;
        *(uint4*)&Xp[((size_t)(bh*SEQ + q0 + row))*HD + ch*8] = *(uint4*)&Xs[(size_t)row*200 + ch*8];
    }
}

// ============================================================
// K5: y = x + sum(X1 partials), LayerNorm — 192 thr, 4 ch/thread
// ============================================================
__global__ __launch_bounds__(192) void k_ln(
    const float* __restrict__ x,
    const float* __restrict__ gamma,
    const float* __restrict__ beta,
    float* __restrict__ out)
{
    int row = blockIdx.x;
    int b_ = row >> 11, s_ = row & (SEQ-1);
    int tid = threadIdx.x;
    int ns = (s_ >> 9) + 1;
    int c = tid*4;

    __shared__ float rs[6], rq[6];
    __shared__ float s_mu, s_inv;

    int h_ = c/HD, d_ = c - h_*HD;
    size_t o = ((size_t)((b_*NH+h_)*SEQ+s_))*HD + d_;
    float4 xv = *(const float4*)&x[(size_t)row*DM + c];
    float v0 = xv.x, v1 = xv.y, v2 = xv.z, v3 = xv.w;
    for (int s = 0; s < ns; s++){
        uint2 hp = *(const uint2*)&g_X1p[(size_t)s*BHT*SEQ*HD + o];
        float2 f0 = __half22float2(*(__half2*)&hp.x);
        float2 f1 = __half22float2(*(__half2*)&hp.y);
        v0 += f0.x; v1 += f0.y; v2 += f1.x; v3 += f1.y;
    }
    float sum = (v0 + v1) + (v2 + v3);
    float sq  = (v0*v0 + v1*v1) + (v2*v2 + v3*v3);

    #pragma unroll
    for (int of = 16; of; of >>= 1){
        sum += __shfl_down_sync(0xffffffffu, sum, of);
        sq  += __shfl_down_sync(0xffffffffu, sq , of);
    }
    int wid = tid >> 5, lane = tid & 31;
    if (lane == 0){ rs[wid] = sum; rq[wid] = sq; }
    __syncthreads();
    if (tid < 32){
        sum = (tid < 6) ? rs[tid] : 0.0f;
        sq  = (tid < 6) ? rq[tid] : 0.0f;
        #pragma unroll
        for (int of = 4; of; of >>= 1){
            sum += __shfl_down_sync(0xffffffffu, sum, of);
            sq  += __shfl_down_sync(0xffffffffu, sq , of);
        }
        if (tid == 0){
            float mu  = sum * (1.0f/DM);
            float var = sq  * (1.0f/DM) - mu*mu;
            s_mu = mu;
            s_inv = rsqrtf(var + 1e-5f);
        }
    }
    __syncthreads();
    float mu = s_mu, inv = s_inv;
    float4 gv = *(const float4*)&gamma[c];
    float4 bv = *(const float4*)&beta[c];
    float4 ov;
    ov.x = (v0 - mu)*inv*gv.x + bv.x;
    ov.y = (v1 - mu)*inv*gv.y + bv.y;
    ov.z = (v2 - mu)*inv*gv.z + bv.z;
    ov.w = (v3 - mu)*inv*gv.w + bv.w;
    *(float4*)&out[(size_t)row*DM + c] = ov;
}

// ============================================================
extern "C" void kernel_launch(void* const* d_in, const int* in_sizes, int n_in,
                              void* d_out, int out_size)
{
    const float*         x     = (const float*)d_in[0];
    const unsigned char* am    = (const unsigned char*)d_in[1];
    const float*         Wq    = (const float*)d_in[2];
    const float*         bq    = (const float*)d_in[3];
    const float*         Wk    = (const float*)d_in[4];
    const float*         bk    = (const float*)d_in[5];
    const float*         Wv    = (const float*)d_in[6];
    const float*         bv    = (const float*)d_in[7];
    const float*         gamma = (const float*)d_in[8];
    const float*         beta  = (const float*)d_in[9];
    float*               out   = (float*)d_out;
    (void)in_sizes; (void)n_in; (void)out_size;

    const int SM_QKV = 2*128*72*2*2;                    // 73728
    const int SM_SC  = 2*128*72*2*2 + 2*128*4;          // 74752
    const int SM_AV  = (2*128*72 + 2*64*200)*2;         // 88064

    cudaFuncSetAttribute(k_qkv,    cudaFuncAttributeMaxDynamicSharedMemorySize, SM_QKV);
    cudaFuncSetAttribute(k_scores, cudaFuncAttributeMaxDynamicSharedMemorySize, SM_SC);
    cudaFuncSetAttribute(k_av,     cudaFuncAttributeMaxDynamicSharedMemorySize, SM_AV);

    k_cvt<<<(NX4 + 3*NW4)/256, 256>>>(x, Wq, Wk, Wv);

    k_qkv<<<dim3(3*DM/128, BATCH*SEQ/128), 256, SM_QKV>>>(bq, bk, bv);

    const int NT = (SEQ/128)*(SEQ/128 + 1)/2;   // 136 lower-tri tiles
    k_scores<<<dim3(NT, BHT), 256, SM_SC>>>(am);

    k_foldv<<<dim3(SEQ/32, BHT), 256>>>();

    k_av<<<dim3(40, BHT), 256, SM_AV>>>();

    k_ln<<<BATCH*SEQ, 192>>>(x, gamma, beta, out);
}